// round 17
// baseline (speedup 1.0000x reference)
#include <cuda_runtime.h>
#include <cstdint>

typedef unsigned long long u64;

// Packed (v,v) pre-scaled weights in GLOBAL memory as 16B pairs.
// Read by the main kernel as broadcast LDG.128 (L1-hit after first touch);
// no constant bank -> no memcpy-to-symbol graph node.
// Pair layout (ulonglong2 index):
//  [2j]    = (W1[j,0], W1[j,1])      j=0..4
//  [2j+1]  = (W1[j,2], b1[j])
//  [10+3j] = (.5W2[j,0], .5W2[j,1])  j=0..4
//  [11+3j] = (.5W2[j,2], .5W2[j,3])
//  [12+3j] = (.5W2[j,4], b2[j])
//  [25]    = (.5W3[0], .5W3[1])
//  [26]    = (.5W3[2], .5W3[3])
//  [27]    = (.5W3[4], b3)
__device__ __align__(16) u64 g_pack[56];

__global__ void pack_weights_kernel(const float* __restrict__ W1, const float* __restrict__ b1,
                                    const float* __restrict__ W2, const float* __restrict__ b2,
                                    const float* __restrict__ W3, const float* __restrict__ b3)
{
    int i = threadIdx.x;
    if (i >= 56) return;
    float v = 0.0f;
    if (i < 20) {
        int j = i >> 2, r = i & 3;
        v = (r < 3) ? W1[3 * j + r] : b1[j];
    } else if (i < 50) {
        int t = i - 20, j = t / 6, r = t - 6 * j;
        v = (r < 5) ? 0.5f * W2[5 * j + r] : b2[j];
    } else if (i < 55) {
        v = 0.5f * W3[i - 50];
    } else {
        v = b3[0];
    }
    unsigned int u = __float_as_uint(v);
    g_pack[i] = ((u64)u << 32) | (u64)u;
}

// ---------- packed f32x2 helpers ----------
__device__ __forceinline__ u64 pk2(float lo, float hi) {
    u64 r;
    asm("mov.b64 %0, {%1, %2};" : "=l"(r)
        : "r"(__float_as_uint(lo)), "r"(__float_as_uint(hi)));
    return r;
}
__device__ __forceinline__ void upk(u64 a, float& lo, float& hi) {
    unsigned int l_, h_;
    asm("mov.b64 {%0, %1}, %2;" : "=r"(l_), "=r"(h_) : "l"(a));
    lo = __uint_as_float(l_);
    hi = __uint_as_float(h_);
}
__device__ __forceinline__ u64 dfma(u64 a, u64 b, u64 c) {
    u64 d;
    asm("fma.rn.f32x2 %0, %1, %2, %3;" : "=l"(d) : "l"(a), "l"(b), "l"(c));
    return d;
}
__device__ __forceinline__ u64 dmul(u64 a, u64 b) {
    u64 d;
    asm("mul.rn.f32x2 %0, %1, %2;" : "=l"(d) : "l"(a), "l"(b));
    return d;
}
__device__ __forceinline__ u64 dadd(u64 a, u64 b) {
    u64 d;
    asm("add.rn.f32x2 %0, %1, %2;" : "=l"(d) : "l"(a), "l"(b));
    return d;
}
// 2*relu(x) per half, exact: x + |x| (2x folded into pre-halved W2/W3)
__device__ __forceinline__ u64 drelu2(u64 a) {
    return dadd(a, a & 0x7FFFFFFF7FFFFFFFULL);
}
// broadcast 16B weight-pair load from global (L1-hit, all lanes same addr)
__device__ __forceinline__ ulonglong2 ldw2(int idx) {
    const ulonglong2* p = reinterpret_cast<const ulonglong2*>(g_pack) + idx;
    return __ldg(p);
}

// One warp = 4 points; 8 lanes per point; each lane loads its own contiguous
// 48B (4 neighbors = 2 packed pairs) and runs ONE dual step. Weights read
// once per thread via broadcast LDG.128 from the packed global buffer.
__global__ void __launch_bounds__(256)
velvec_kernel(const float* __restrict__ pos, const float* __restrict__ nbr,
              float* __restrict__ out, int N)
{
    int gw = (blockIdx.x * blockDim.x + threadIdx.x) >> 5;  // global warp id
    int l = threadIdx.x & 31;
    int p = l >> 3;            // point within warp's group of 4
    int j = l & 7;             // 48B slice within the point's 384B row
    int n = gw * 4 + p;        // global point index
    int nc = (n < N) ? n : (N - 1);   // clamped for loads; store predicated

    // ---- load this lane's 4 neighbors (3x LDG.128, contiguous 48B) ----
    const float4* bp = reinterpret_cast<const float4*>(
        (const char*)nbr + (size_t)nc * 384 + (size_t)j * 48);
    float4 q0 = __ldg(bp + 0);    // x0 y0 z0 x1
    float4 q1 = __ldg(bp + 1);    // y1 z1 x2 y2
    float4 q2 = __ldg(bp + 2);    // z2 x3 y3 z3

    float px = __ldg(pos + 3 * nc + 0);
    float py = __ldg(pos + 3 * nc + 1);
    float pz = __ldg(pos + 3 * nc + 2);
    u64 npx = pk2(-px, -px), npy = pk2(-py, -py), npz = pk2(-pz, -pz);

    // pair A = neighbors 0,1 of the slice; pair B = neighbors 2,3
    u64 axA = pk2(q0.x, q0.w), ayA = pk2(q0.y, q1.x), azA = pk2(q0.z, q1.y);
    u64 axB = pk2(q1.z, q2.y), ayB = pk2(q1.w, q2.z), azB = pk2(q2.x, q2.w);

    u64 dxA = dadd(axA, npx), dyA = dadd(ayA, npy), dzA = dadd(azA, npz);
    u64 dxB = dadd(axB, npx), dyB = dadd(ayB, npy), dzB = dadd(azB, npz);
    u64 d2A = dfma(dxA, dxA, dfma(dyA, dyA, dmul(dzA, dzA)));
    u64 d2B = dfma(dxB, dxB, dfma(dyB, dyB, dmul(dzB, dzB)));
    float a0, a1, b0, b1v;
    upk(d2A, a0, a1); upk(d2B, b0, b1v);
    float iA0 = rsqrtf(fmaxf(a0, 1e-24f));   // matches v/max(||v||,1e-12)
    float iA1 = rsqrtf(fmaxf(a1, 1e-24f));
    float iB0 = rsqrtf(fmaxf(b0, 1e-24f));
    float iB1 = rsqrtf(fmaxf(b1v, 1e-24f));

    // Layer 1 on UNNORMALIZED diffs (overlaps the MUFU rsqrt).
    u64 uA0, uA1, uA2, uA3, uA4, uB0, uB1, uB2, uB3, uB4;
    u64 B0, B1, B2, B3, B4;
#define L1ROW(UA, UB, BB, J)                                                \
    {                                                                       \
        ulonglong2 t0 = ldw2(2 * (J));                                      \
        ulonglong2 t1 = ldw2(2 * (J) + 1);                                  \
        UA = dfma(dzA, t1.x, dfma(dyA, t0.y, dmul(dxA, t0.x)));             \
        UB = dfma(dzB, t1.x, dfma(dyB, t0.y, dmul(dxB, t0.x)));             \
        BB = t1.y;                                                          \
    }
    L1ROW(uA0, uB0, B0, 0) L1ROW(uA1, uB1, B1, 1) L1ROW(uA2, uB2, B2, 2)
    L1ROW(uA3, uB3, B3, 3) L1ROW(uA4, uB4, B4, 4)
#undef L1ROW

    u64 invA = pk2(iA0, iA1);
    u64 invB = pk2(iB0, iB1);

    u64 hA0 = drelu2(dfma(uA0, invA, B0)), hB0 = drelu2(dfma(uB0, invB, B0));
    u64 hA1 = drelu2(dfma(uA1, invA, B1)), hB1 = drelu2(dfma(uB1, invB, B1));
    u64 hA2 = drelu2(dfma(uA2, invA, B2)), hB2 = drelu2(dfma(uB2, invB, B2));
    u64 hA3 = drelu2(dfma(uA3, invA, B3)), hB3 = drelu2(dfma(uB3, invB, B3));
    u64 hA4 = drelu2(dfma(uA4, invA, B4)), hB4 = drelu2(dfma(uB4, invB, B4));

    // Layer 2 (weights pre-scaled by 0.5): 3 broadcast LDG.128 per row
    u64 gA0, gA1, gA2, gA3, gA4, gB0, gB1, gB2, gB3, gB4;
#define L2ROW(GA, GB, J)                                                    \
    {                                                                       \
        ulonglong2 p0 = ldw2(10 + 3 * (J));                                 \
        ulonglong2 p1 = ldw2(11 + 3 * (J));                                 \
        ulonglong2 p2 = ldw2(12 + 3 * (J));                                 \
        GA = dfma(hA0, p0.x, p2.y); GA = dfma(hA1, p0.y, GA);               \
        GA = dfma(hA2, p1.x, GA);   GA = dfma(hA3, p1.y, GA);               \
        GA = dfma(hA4, p2.x, GA);   GA = drelu2(GA);                        \
        GB = dfma(hB0, p0.x, p2.y); GB = dfma(hB1, p0.y, GB);               \
        GB = dfma(hB2, p1.x, GB);   GB = dfma(hB3, p1.y, GB);               \
        GB = dfma(hB4, p2.x, GB);   GB = drelu2(GB);                        \
    }
    L2ROW(gA0, gB0, 0) L2ROW(gA1, gB1, 1) L2ROW(gA2, gB2, 2)
    L2ROW(gA3, gB3, 3) L2ROW(gA4, gB4, 4)
#undef L2ROW

    // Layer 3 (pre-scaled by 0.5): 3 broadcast LDG.128
    ulonglong2 q0p = ldw2(25), q1p = ldw2(26), q2p = ldw2(27);
    u64 wgA = dfma(gA0, q0p.x, q2p.y);
    wgA = dfma(gA1, q0p.y, wgA); wgA = dfma(gA2, q1p.x, wgA);
    wgA = dfma(gA3, q1p.y, wgA); wgA = dfma(gA4, q2p.x, wgA);
    u64 wgB = dfma(gB0, q0p.x, q2p.y);
    wgB = dfma(gB1, q0p.y, wgB); wgB = dfma(gB2, q1p.x, wgB);
    wgB = dfma(gB3, q1p.y, wgB); wgB = dfma(gB4, q2p.x, wgB);

    // vel contribution: d * (inv * w)
    u64 wiA = dmul(wgA, invA);
    u64 wiB = dmul(wgB, invB);
    u64 vx = dmul(dxA, wiA), vy = dmul(dyA, wiA), vz = dmul(dzA, wiA);
    vx = dfma(dxB, wiB, vx); vy = dfma(dyB, wiB, vy); vz = dfma(dzB, wiB, vz);

    // collapse packed halves, then reduce across the 8-lane cluster
    float x0, x1, y0, y1, z0, z1;
    upk(vx, x0, x1); upk(vy, y0, y1); upk(vz, z0, z1);
    float fx = x0 + x1, fy = y0 + y1, fz = z0 + z1;
    fx += __shfl_xor_sync(0xFFFFFFFFu, fx, 1);
    fy += __shfl_xor_sync(0xFFFFFFFFu, fy, 1);
    fz += __shfl_xor_sync(0xFFFFFFFFu, fz, 1);
    fx += __shfl_xor_sync(0xFFFFFFFFu, fx, 2);
    fy += __shfl_xor_sync(0xFFFFFFFFu, fy, 2);
    fz += __shfl_xor_sync(0xFFFFFFFFu, fz, 2);
    fx += __shfl_xor_sync(0xFFFFFFFFu, fx, 4);
    fy += __shfl_xor_sync(0xFFFFFFFFu, fy, 4);
    fz += __shfl_xor_sync(0xFFFFFFFFu, fz, 4);

    if (j == 0 && n < N) {
        float d2 = fmaf(fx, fx, fmaf(fy, fy, fz * fz));
        d2 = fmaxf(d2, 1e-24f);
        float r = rsqrtf(d2);
        r = r * fmaf(-0.5f * d2 * r, r, 1.5f);  // one Newton step
        out[3 * n + 0] = fx * r;
        out[3 * n + 1] = fy * r;
        out[3 * n + 2] = fz * r;
    }
}

extern "C" void kernel_launch(void* const* d_in, const int* in_sizes, int n_in,
                              void* d_out, int out_size)
{
    const float* pos = (const float*)d_in[0];
    const float* nbr = (const float*)d_in[1];
    const float* W1  = (const float*)d_in[2];
    const float* b1  = (const float*)d_in[3];
    const float* W2  = (const float*)d_in[4];
    const float* b2  = (const float*)d_in[5];
    const float* W3  = (const float*)d_in[6];
    const float* b3  = (const float*)d_in[7];
    float* out = (float*)d_out;

    // 1) pack + pre-scale weights (paired order) into the global buffer
    pack_weights_kernel<<<1, 64>>>(W1, b1, W2, b2, W3, b3);

    // 2) main kernel: one warp per 4 points, 8 lanes per point
    int N = in_sizes[0] / 3;                 // positions is [N,3]
    long long warps = (N + 3) / 4;           // 4 points per warp
    int threads = 256;
    long long blocks = (warps * 32 + threads - 1) / threads;
    velvec_kernel<<<(int)blocks, threads>>>(pos, nbr, out, N);
}